// round 1
// baseline (speedup 1.0000x reference)
#include <cuda_runtime.h>
#include <math.h>

#define Bsz 2
#define Lseq 4096
#define DM 768
#define DS 16
#define DC 4
#define EE 1536
#define NROWS (Bsz*Lseq)      // 8192
#define NPACK (DM + DS + DS)  // 800: [0,768)=xs, [768,784)=ds, [784,800)=dt_raw
#define LN_EPS 1e-5f

// ---------------- scratch (static device allocations; no cudaMalloc) -------
__device__ float g_xn   [NROWS * DM];     // LN output
__device__ float g_xin  [NROWS * EE];     // in-proj output
__device__ float g_xact [NROWS * EE];     // conv + silu output
__device__ float g_wpack[EE * NPACK];     // [W_xp | W_dt]
__device__ float g_bpack[NPACK];
__device__ float g_xd   [NROWS * NPACK];  // xs | ds | dt_raw
__device__ float g_dt   [NROWS * DS];
__device__ float g_bt   [NROWS * DS];
__device__ float g_v    [NROWS * DS];
__device__ float g_y    [NROWS * DM];

// ---------------- LayerNorm -------------------------------------------------
__global__ __launch_bounds__(256) void ln_kernel(const float* __restrict__ x,
                                                 const float* __restrict__ g,
                                                 const float* __restrict__ b) {
    int row = blockIdx.x;
    int tid = threadIdx.x;
    const float* xr = x + (size_t)row * DM;
    float v0 = xr[tid], v1 = xr[tid + 256], v2 = xr[tid + 512];

    __shared__ float red[256];
    float s = v0 + v1 + v2;
    red[tid] = s; __syncthreads();
    for (int off = 128; off > 0; off >>= 1) {
        if (tid < off) red[tid] += red[tid + off];
        __syncthreads();
    }
    float mu = red[0] * (1.0f / DM);
    __syncthreads();

    float d0 = v0 - mu, d1 = v1 - mu, d2 = v2 - mu;
    red[tid] = d0*d0 + d1*d1 + d2*d2; __syncthreads();
    for (int off = 128; off > 0; off >>= 1) {
        if (tid < off) red[tid] += red[tid + off];
        __syncthreads();
    }
    float rstd = rsqrtf(red[0] * (1.0f / DM) + LN_EPS);

    float* o = g_xn + (size_t)row * DM;
    o[tid]       = d0 * rstd * g[tid]       + b[tid];
    o[tid + 256] = d1 * rstd * g[tid + 256] + b[tid + 256];
    o[tid + 512] = d2 * rstd * g[tid + 512] + b[tid + 512];
}

// ---------------- pack W_xp/W_dt into one weight ---------------------------
__global__ void pack_kernel(const float* __restrict__ W_xp, const float* __restrict__ b_xp,
                            const float* __restrict__ W_dt, const float* __restrict__ b_dt) {
    int idx = blockIdx.x * blockDim.x + threadIdx.x;
    int total = EE * NPACK;
    if (idx < total) {
        int k = idx / NPACK, n = idx % NPACK;
        g_wpack[idx] = (n < DM + DS) ? W_xp[k * (DM + DS) + n]
                                     : W_dt[k * DS + (n - (DM + DS))];
    }
    if (idx < NPACK)
        g_bpack[idx] = (idx < DM + DS) ? b_xp[idx] : b_dt[idx - (DM + DS)];
}

// ---------------- generic tiled SGEMM: C = A(MxK) * B(KxN) (+bias)(+C) ------
// M multiple of 128, K multiple of 8 (all our calls satisfy this).
__global__ __launch_bounds__(256) void sgemm128(
    const float* __restrict__ A, int lda,
    const float* __restrict__ B, int ldb,
    const float* __restrict__ bias,
    float* __restrict__ C, int ldc,
    int N, int K, int accumulate)
{
    __shared__ float As[8][128];
    __shared__ float Bs[8][128];
    int tid = threadIdx.x;
    int m0 = blockIdx.y * 128, n0 = blockIdx.x * 128;

    int aRow = tid >> 1;            // 0..127
    int aCol = (tid & 1) * 4;       // 0 or 4
    int bRow = tid >> 5;            // 0..7
    int bCol = (tid & 31) * 4;      // 0..124

    int tx = tid & 15, ty = tid >> 4;
    float acc[8][8];
    #pragma unroll
    for (int i = 0; i < 8; i++)
        #pragma unroll
        for (int j = 0; j < 8; j++) acc[i][j] = 0.0f;

    const float* Aptr = A + (size_t)(m0 + aRow) * lda + aCol;
    int ncol = n0 + bCol;

    for (int k0 = 0; k0 < K; k0 += 8) {
        float4 av = *(const float4*)(Aptr + k0);
        As[aCol + 0][aRow] = av.x;
        As[aCol + 1][aRow] = av.y;
        As[aCol + 2][aRow] = av.z;
        As[aCol + 3][aRow] = av.w;

        float4 bv = make_float4(0.f, 0.f, 0.f, 0.f);
        const float* Brow = B + (size_t)(k0 + bRow) * ldb;
        if (ncol + 3 < N) {
            bv = *(const float4*)(Brow + ncol);
        } else {
            if (ncol + 0 < N) bv.x = Brow[ncol + 0];
            if (ncol + 1 < N) bv.y = Brow[ncol + 1];
            if (ncol + 2 < N) bv.z = Brow[ncol + 2];
            if (ncol + 3 < N) bv.w = Brow[ncol + 3];
        }
        *(float4*)&Bs[bRow][bCol] = bv;
        __syncthreads();

        #pragma unroll
        for (int kk = 0; kk < 8; kk++) {
            float4 a0 = *(const float4*)&As[kk][ty * 8];
            float4 a1 = *(const float4*)&As[kk][ty * 8 + 4];
            float4 b0 = *(const float4*)&Bs[kk][tx * 8];
            float4 b1 = *(const float4*)&Bs[kk][tx * 8 + 4];
            float ra[8] = {a0.x, a0.y, a0.z, a0.w, a1.x, a1.y, a1.z, a1.w};
            float rb[8] = {b0.x, b0.y, b0.z, b0.w, b1.x, b1.y, b1.z, b1.w};
            #pragma unroll
            for (int i = 0; i < 8; i++)
                #pragma unroll
                for (int j = 0; j < 8; j++)
                    acc[i][j] = fmaf(ra[i], rb[j], acc[i][j]);
        }
        __syncthreads();
    }

    #pragma unroll
    for (int i = 0; i < 8; i++) {
        size_t m = m0 + ty * 8 + i;
        #pragma unroll
        for (int j = 0; j < 8; j++) {
            int n = n0 + tx * 8 + j;
            if (n < N) {
                float c = acc[i][j];
                if (bias) c += bias[n];
                if (accumulate) c += C[m * ldc + n];
                C[m * ldc + n] = c;
            }
        }
    }
}

// ---------------- depthwise causal conv (k=4) + SiLU ------------------------
__global__ void conv_silu_kernel(const float* __restrict__ b_conv,
                                 const float* __restrict__ W_conv) {
    int idx = blockIdx.x * blockDim.x + threadIdx.x;
    if (idx >= NROWS * EE) return;
    int e = idx % EE;
    int r = idx / EE;
    int l = r % Lseq;

    float w0 = W_conv[e * 4 + 0], w1 = W_conv[e * 4 + 1];
    float w2 = W_conv[e * 4 + 2], w3 = W_conv[e * 4 + 3];
    float s = b_conv[e];
    if (l >= 3) s += g_xin[(size_t)(r - 3) * EE + e] * w0;
    if (l >= 2) s += g_xin[(size_t)(r - 2) * EE + e] * w1;
    if (l >= 1) s += g_xin[(size_t)(r - 1) * EE + e] * w2;
    s += g_xin[(size_t)r * EE + e] * w3;
    // silu
    float act = s / (1.0f + expf(-s));
    g_xact[idx] = act;
}

// ---------------- pre-scan elementwise: dt = softplus, bt = ds*exp(-dt/2) ---
__global__ void prescan_kernel() {
    int idx = blockIdx.x * blockDim.x + threadIdx.x;
    if (idx >= NROWS * DS) return;
    int row = idx / DS, s = idx % DS;
    float dtraw = g_xd[(size_t)row * NPACK + (DM + DS) + s];
    float ds    = g_xd[(size_t)row * NPACK + DM + s];
    float dt = fmaxf(dtraw, 0.0f) + log1pf(expf(-fabsf(dtraw)));
    g_dt[idx] = dt;
    g_bt[idx] = ds * expf(-0.5f * dt);
}

// ---------------- parallel scan: v_t = a_t v_{t-1} + b_t --------------------
// one block per (batch, state) channel; 256 threads x 16 steps each
__global__ __launch_bounds__(256) void scan_kernel() {
    int chan = blockIdx.x;            // 0..31
    int bb = chan / DS, s = chan % DS;
    int t = threadIdx.x;

    __shared__ float sA[256], sB[256];
    // local segment compose
    float A = 1.0f, Bl = 0.0f;
    int base = bb * Lseq;
    #pragma unroll 4
    for (int i = 0; i < 16; i++) {
        int l = t * 16 + i;
        size_t off = (size_t)(base + l) * DS + s;
        float a = expf(-g_dt[off]);
        float bt = g_bt[off];
        A = a * A;
        Bl = a * Bl + bt;
    }
    sA[t] = A; sB[t] = Bl;
    __syncthreads();
    // inclusive Hillis-Steele scan with (A,B) composition
    for (int offp = 1; offp < 256; offp <<= 1) {
        float pA = 0.f, pB = 0.f;
        bool has = (t >= offp);
        if (has) { pA = sA[t - offp]; pB = sB[t - offp]; }
        __syncthreads();
        if (has) { sB[t] = sA[t] * pB + sB[t]; sA[t] = sA[t] * pA; }
        __syncthreads();
    }
    float v = (t == 0) ? 0.0f : sB[t - 1];   // exclusive carry (v0 = 0)
    // replay segment with carry, writing v
    for (int i = 0; i < 16; i++) {
        int l = t * 16 + i;
        size_t off = (size_t)(base + l) * DS + s;
        float a = expf(-g_dt[off]);
        float bt = g_bt[off];
        v = a * v + bt;
        g_v[off] = v;
    }
}

// ---------------- us computation + K=16 GEMM + xs add -> y ------------------
__global__ __launch_bounds__(256) void us_y_kernel(const float* __restrict__ W_us,
                                                   const float* __restrict__ b_us) {
    int row = blockIdx.x;
    int tid = threadIdx.x;
    int l = row % Lseq;
    float kf = (float)(Lseq - 1 - l);

    __shared__ float us_sh[DS];
    if (tid < DS) {
        size_t off = (size_t)row * DS + tid;
        float dt = g_dt[off];
        float v  = g_v[off];
        float bt = g_bt[off];
        float denom = expm1f(-dt);
        if (denom > -1e-30f) denom = -1e-30f;
        us_sh[tid] = expf(-kf * dt) * v + bt * expm1f(-kf * dt) / denom;
    }
    __syncthreads();

    #pragma unroll
    for (int j = 0; j < 3; j++) {
        int d = tid + j * 256;
        float acc = g_xd[(size_t)row * NPACK + d] + b_us[d];   // xs + bias
        #pragma unroll
        for (int s = 0; s < DS; s++)
            acc = fmaf(us_sh[s], W_us[s * DM + d], acc);
        g_y[(size_t)row * DM + d] = acc;
    }
}

// ---------------- launch ----------------------------------------------------
extern "C" void kernel_launch(void* const* d_in, const int* in_sizes, int n_in,
                              void* d_out, int out_size) {
    const float* x      = (const float*)d_in[0];
    const float* ln_g   = (const float*)d_in[1];
    const float* ln_b   = (const float*)d_in[2];
    const float* W_in   = (const float*)d_in[3];
    const float* b_in   = (const float*)d_in[4];
    const float* W_conv = (const float*)d_in[5];
    const float* b_conv = (const float*)d_in[6];
    const float* W_xp   = (const float*)d_in[7];
    const float* b_xp   = (const float*)d_in[8];
    const float* W_dt   = (const float*)d_in[9];
    const float* b_dt   = (const float*)d_in[10];
    const float* W_us   = (const float*)d_in[11];
    const float* b_us   = (const float*)d_in[12];
    const float* W_out  = (const float*)d_in[13];
    const float* b_out  = (const float*)d_in[14];
    float* out = (float*)d_out;

    float* xn   = nullptr; cudaGetSymbolAddress((void**)&xn,   g_xn);
    float* xin  = nullptr; cudaGetSymbolAddress((void**)&xin,  g_xin);
    float* xact = nullptr; cudaGetSymbolAddress((void**)&xact, g_xact);
    float* wp   = nullptr; cudaGetSymbolAddress((void**)&wp,   g_wpack);
    float* bp   = nullptr; cudaGetSymbolAddress((void**)&bp,   g_bpack);
    float* xd   = nullptr; cudaGetSymbolAddress((void**)&xd,   g_xd);
    float* yb   = nullptr; cudaGetSymbolAddress((void**)&yb,   g_y);

    // 1. LayerNorm
    ln_kernel<<<NROWS, 256>>>(x, ln_g, ln_b);

    // 2. in-proj GEMM: xn(8192x768) @ W_in(768x1536) + b_in -> xin
    {
        dim3 grid(EE / 128, NROWS / 128);
        sgemm128<<<grid, 256>>>(xn, DM, W_in, EE, b_in, xin, EE, EE, DM, 0);
    }

    // 3. pack [W_xp | W_dt]
    {
        int total = EE * NPACK;
        pack_kernel<<<(total + 255) / 256, 256>>>(W_xp, b_xp, W_dt, b_dt);
    }

    // 4. depthwise conv + silu -> xact
    conv_silu_kernel<<<(NROWS * EE + 255) / 256, 256>>>(b_conv, W_conv);

    // 5. packed GEMM: xact(8192x1536) @ wpack(1536x800) + bpack -> xd
    {
        dim3 grid((NPACK + 127) / 128, NROWS / 128);
        sgemm128<<<grid, 256>>>(xact, EE, wp, NPACK, bp, xd, NPACK, NPACK, EE, 0);
    }

    // 6. pre-scan elementwise
    prescan_kernel<<<(NROWS * DS + 255) / 256, 256>>>();

    // 7. parallel scan (32 channels)
    scan_kernel<<<Bsz * DS, 256>>>();

    // 8. us + xs + us@W_us + b_us -> y
    us_y_kernel<<<NROWS, 256>>>(W_us, b_us);

    // 9. out = y @ W_out[0:768,:] + b_out
    {
        dim3 grid(DM / 128, NROWS / 128);
        sgemm128<<<grid, 256>>>(yb, DM, W_out, DM, b_out, out, DM, DM, DM, 0);
    }
    // 10. out += xact[:,768:] @ W_out[768:,:]
    {
        dim3 grid(DM / 128, NROWS / 128);
        sgemm128<<<grid, 256>>>(xact + DM, EE, W_out + (size_t)DM * DM, DM,
                                nullptr, out, DM, DM, DM, 1);
    }
}

// round 3
// speedup vs baseline: 2.7179x; 2.7179x over previous
#include <cuda_runtime.h>
#include <cstdint>
#include <math.h>

#define Bsz 2
#define Lseq 4096
#define DM 768
#define DS 16
#define EE 1536
#define NROWS (Bsz*Lseq)      // 8192
#define NPACK (DM + DS + DS)  // 800
#define LN_EPS 1e-5f

#define KPAD 36
#define STAGE_F (2 * 128 * KPAD)   // floats per pipeline stage (A tile + B tile)

// ======================= small PTX helpers ==================================
__device__ __forceinline__ uint32_t smem_u32(const void* p) {
    uint32_t a;
    asm("{ .reg .u64 t; cvta.to.shared.u64 t, %1; cvt.u32.u64 %0, t; }"
        : "=r"(a) : "l"(p));
    return a;
}
__device__ __forceinline__ void cp_async16(uint32_t dst, const void* src, uint32_t sz) {
    asm volatile("cp.async.cg.shared.global [%0], [%1], 16, %2;"
                 :: "r"(dst), "l"(src), "r"(sz) : "memory");
}
__device__ __forceinline__ void cp_commit() {
    asm volatile("cp.async.commit_group;" ::: "memory");
}
template<int N> __device__ __forceinline__ void cp_wait() {
    asm volatile("cp.async.wait_group %0;" :: "n"(N) : "memory");
}
__device__ __forceinline__ uint32_t f2tf32(float x) {
    uint32_t r;
    asm("cvt.rna.tf32.f32 %0, %1;" : "=r"(r) : "f"(x));
    return r;
}
__device__ __forceinline__ void mma_tf32(float* c, const uint32_t* a, const uint32_t* b) {
    asm volatile("mma.sync.aligned.m16n8k8.row.col.f32.tf32.tf32.f32 "
        "{%0,%1,%2,%3}, {%4,%5,%6,%7}, {%8,%9}, {%0,%1,%2,%3};"
        : "+f"(c[0]), "+f"(c[1]), "+f"(c[2]), "+f"(c[3])
        : "r"(a[0]), "r"(a[1]), "r"(a[2]), "r"(a[3]), "r"(b[0]), "r"(b[1]));
}

// ======================= scratch ============================================
__device__ float g_xn    [NROWS * DM];
__device__ float g_xin   [NROWS * EE];
__device__ float g_xact  [NROWS * EE];
__device__ float g_cat   [NROWS * EE];     // [y | xact_hi]
__device__ float g_xd    [NROWS * NPACK];
__device__ float g_dt    [NROWS * DS];
__device__ float g_bt    [NROWS * DS];
__device__ float g_v     [NROWS * DS];
__device__ float g_wpack [EE * NPACK];
__device__ float g_bpack [NPACK];
__device__ float g_winT  [EE * DM];        // [1536][768]
__device__ float g_wpackT[NPACK * EE];     // [800][1536]
__device__ float g_woutT [DM * EE];        // [768][1536]

// ======================= tf32 mma.sync GEMM =================================
// C[M, Ndim] = A[M, K](row) @ Bt[Ndim, K](row)^T + bias
// Block tile 128x128, K-chunk 32, 2-stage cp.async double buffer.
// 8 warps: warp_m = wid>>1 (0..3), warp_n = wid&1 (0..1); warp tile 32m x 64n.
__global__ __launch_bounds__(256, 2) void gemm_tf32_kernel(
    const float* __restrict__ A, int lda,
    const float* __restrict__ Bt, int Ndim,
    const float* __restrict__ bias,
    float* __restrict__ C, int ldc, int K)
{
    extern __shared__ __align__(16) float sm[];
    const int tid = threadIdx.x;
    const int wid = tid >> 5, lane = tid & 31;
    const int wm = wid >> 1, wn = wid & 1;
    const int g = lane >> 2, tg = lane & 3;
    const int m0 = blockIdx.y * 128, n0 = blockIdx.x * 128;
    const int NC = K >> 5;

    // ---- loader mapping: thread t loads 16 floats of one row of each tile
    const int tr = tid >> 1;             // 0..127
    const int tc = (tid & 1) * 16;       // 0 or 16
    const int gn = n0 + tr;
    const uint32_t bsz = (gn < Ndim) ? 16u : 0u;
    const float* arow = A + (size_t)(m0 + tr) * lda + tc;
    const float* brow = Bt + (size_t)(gn < Ndim ? gn : 0) * K + tc;
    const uint32_t a_off = (uint32_t)(tr * KPAD + tc) * 4u;
    const uint32_t smb = smem_u32(sm);

    auto load_chunk = [&](int c) {
        const int s = c & 1;
        uint32_t dA = smb + (uint32_t)s * (STAGE_F * 4u) + a_off;
        uint32_t dB = dA + 128u * KPAD * 4u;
        const float* ga = arow + c * 32;
        const float* gb = brow + c * 32;
        #pragma unroll
        for (int i = 0; i < 4; i++) {
            cp_async16(dA + i * 16u, ga + i * 4, 16u);
            cp_async16(dB + i * 16u, gb + i * 4, bsz);
        }
        cp_commit();
    };

    float acc[2][8][4];
    #pragma unroll
    for (int mi = 0; mi < 2; mi++)
        #pragma unroll
        for (int ni = 0; ni < 8; ni++)
            #pragma unroll
            for (int q = 0; q < 4; q++) acc[mi][ni][q] = 0.0f;

    load_chunk(0);
    if (NC > 1) load_chunk(1); else cp_commit();

    for (int c = 0; c < NC; c++) {
        const int s = c & 1;
        cp_wait<1>();
        __syncthreads();

        const float* as = sm + s * STAGE_F + (wm * 32) * KPAD;
        const float* bs = sm + s * STAGE_F + 128 * KPAD + (wn * 64) * KPAD;

        #pragma unroll
        for (int kk = 0; kk < 4; kk++) {
            const int k = kk * 8 + tg;
            uint32_t af[2][4], bf[8][2];
            #pragma unroll
            for (int mi = 0; mi < 2; mi++) {
                const float* ap = as + mi * 16 * KPAD;
                af[mi][0] = f2tf32(ap[(g    ) * KPAD + k    ]);
                af[mi][1] = f2tf32(ap[(g + 8) * KPAD + k    ]);
                af[mi][2] = f2tf32(ap[(g    ) * KPAD + k + 4]);
                af[mi][3] = f2tf32(ap[(g + 8) * KPAD + k + 4]);
            }
            #pragma unroll
            for (int ni = 0; ni < 8; ni++) {
                const float* bp = bs + (ni * 8 + g) * KPAD;
                bf[ni][0] = f2tf32(bp[k    ]);
                bf[ni][1] = f2tf32(bp[k + 4]);
            }
            #pragma unroll
            for (int mi = 0; mi < 2; mi++)
                #pragma unroll
                for (int ni = 0; ni < 8; ni++)
                    mma_tf32(acc[mi][ni], af[mi], bf[ni]);
        }

        __syncthreads();
        if (c + 2 < NC) load_chunk(c + 2); else cp_commit();
    }

    // ---- epilogue: direct register -> global, +bias
    #pragma unroll
    for (int mi = 0; mi < 2; mi++) {
        const int row = m0 + wm * 32 + mi * 16 + g;
        float* c0 = C + (size_t)row * ldc;
        float* c1 = C + (size_t)(row + 8) * ldc;
        #pragma unroll
        for (int ni = 0; ni < 8; ni++) {
            const int col = n0 + wn * 64 + ni * 8 + tg * 2;
            if (col < Ndim) {
                float bx = bias[col], by = bias[col + 1];
                float2 v0 = make_float2(acc[mi][ni][0] + bx, acc[mi][ni][1] + by);
                float2 v1 = make_float2(acc[mi][ni][2] + bx, acc[mi][ni][3] + by);
                *(float2*)(c0 + col) = v0;
                *(float2*)(c1 + col) = v1;
            }
        }
    }
}

// ======================= LayerNorm ==========================================
__global__ __launch_bounds__(256) void ln_kernel(const float* __restrict__ x,
                                                 const float* __restrict__ g,
                                                 const float* __restrict__ b) {
    int row = blockIdx.x, tid = threadIdx.x;
    const float* xr = x + (size_t)row * DM;
    float v0 = xr[tid], v1 = xr[tid + 256], v2 = xr[tid + 512];
    __shared__ float red[256];
    red[tid] = v0 + v1 + v2; __syncthreads();
    for (int off = 128; off > 0; off >>= 1) {
        if (tid < off) red[tid] += red[tid + off];
        __syncthreads();
    }
    float mu = red[0] * (1.0f / DM); __syncthreads();
    float d0 = v0 - mu, d1 = v1 - mu, d2 = v2 - mu;
    red[tid] = d0*d0 + d1*d1 + d2*d2; __syncthreads();
    for (int off = 128; off > 0; off >>= 1) {
        if (tid < off) red[tid] += red[tid + off];
        __syncthreads();
    }
    float rstd = rsqrtf(red[0] * (1.0f / DM) + LN_EPS);
    float* o = g_xn + (size_t)row * DM;
    o[tid]       = d0 * rstd * g[tid]       + b[tid];
    o[tid + 256] = d1 * rstd * g[tid + 256] + b[tid + 256];
    o[tid + 512] = d2 * rstd * g[tid + 512] + b[tid + 512];
}

// ======================= transposes / packing ===============================
__global__ void transpose32(const float* __restrict__ W, float* __restrict__ Wt,
                            int R, int C) {  // W: RxC -> Wt: CxR
    __shared__ float t[32][33];
    int bx = blockIdx.x * 32, by = blockIdx.y * 32;
    int x = bx + threadIdx.x;
    #pragma unroll
    for (int i = 0; i < 32; i += 8) {
        int y = by + threadIdx.y + i;
        if (x < C && y < R) t[threadIdx.y + i][threadIdx.x] = W[(size_t)y * C + x];
    }
    __syncthreads();
    x = by + threadIdx.x;
    #pragma unroll
    for (int i = 0; i < 32; i += 8) {
        int y = bx + threadIdx.y + i;
        if (x < R && y < C) Wt[(size_t)y * R + x] = t[threadIdx.x][threadIdx.y + i];
    }
}

__global__ void pack_kernel(const float* __restrict__ W_xp, const float* __restrict__ b_xp,
                            const float* __restrict__ W_dt, const float* __restrict__ b_dt) {
    int idx = blockIdx.x * blockDim.x + threadIdx.x;
    if (idx < EE * NPACK) {
        int k = idx / NPACK, n = idx % NPACK;
        g_wpack[idx] = (n < DM + DS) ? W_xp[k * (DM + DS) + n]
                                     : W_dt[k * DS + (n - (DM + DS))];
    }
    if (idx < NPACK)
        g_bpack[idx] = (idx < DM + DS) ? b_xp[idx] : b_dt[idx - (DM + DS)];
}

// ======================= depthwise conv (k=4) + SiLU, 4 rows/thread =========
__global__ void conv_silu_kernel(const float* __restrict__ b_conv,
                                 const float* __restrict__ W_conv) {
    int idx = blockIdx.x * blockDim.x + threadIdx.x;
    if (idx >= (NROWS / 4) * EE) return;
    int e = idx % EE;
    int rb = idx / EE;
    int r0 = rb * 4;
    int l0 = r0 % Lseq;
    const float4 w = *(const float4*)(W_conv + e * 4);
    float bc = b_conv[e];
    float x0 = (l0 >= 3) ? g_xin[(size_t)(r0 - 3) * EE + e] : 0.f;
    float x1 = (l0 >= 2) ? g_xin[(size_t)(r0 - 2) * EE + e] : 0.f;
    float x2 = (l0 >= 1) ? g_xin[(size_t)(r0 - 1) * EE + e] : 0.f;
    float x3 = g_xin[(size_t)(r0 + 0) * EE + e];
    float x4 = g_xin[(size_t)(r0 + 1) * EE + e];
    float x5 = g_xin[(size_t)(r0 + 2) * EE + e];
    float x6 = g_xin[(size_t)(r0 + 3) * EE + e];
    float s0 = bc + x0 * w.x + x1 * w.y + x2 * w.z + x3 * w.w;
    float s1 = bc + x1 * w.x + x2 * w.y + x3 * w.z + x4 * w.w;
    float s2 = bc + x2 * w.x + x3 * w.y + x4 * w.z + x5 * w.w;
    float s3 = bc + x3 * w.x + x4 * w.y + x5 * w.z + x6 * w.w;
    float a0 = s0 / (1.0f + expf(-s0));
    float a1 = s1 / (1.0f + expf(-s1));
    float a2 = s2 / (1.0f + expf(-s2));
    float a3 = s3 / (1.0f + expf(-s3));
    g_xact[(size_t)(r0 + 0) * EE + e] = a0;
    g_xact[(size_t)(r0 + 1) * EE + e] = a1;
    g_xact[(size_t)(r0 + 2) * EE + e] = a2;
    g_xact[(size_t)(r0 + 3) * EE + e] = a3;
    if (e >= DM) {  // feed concat buffer for out-proj
        g_cat[(size_t)(r0 + 0) * EE + e] = a0;
        g_cat[(size_t)(r0 + 1) * EE + e] = a1;
        g_cat[(size_t)(r0 + 2) * EE + e] = a2;
        g_cat[(size_t)(r0 + 3) * EE + e] = a3;
    }
}

// ======================= pre-scan elementwise ================================
__global__ void prescan_kernel() {
    int idx = blockIdx.x * blockDim.x + threadIdx.x;
    if (idx >= NROWS * DS) return;
    int row = idx / DS, s = idx % DS;
    float dtraw = g_xd[(size_t)row * NPACK + (DM + DS) + s];
    float ds    = g_xd[(size_t)row * NPACK + DM + s];
    float dt = fmaxf(dtraw, 0.0f) + log1pf(expf(-fabsf(dtraw)));
    g_dt[idx] = dt;
    g_bt[idx] = ds * expf(-0.5f * dt);
}

// ======================= parallel scan ======================================
__global__ __launch_bounds__(256) void scan_kernel() {
    int chan = blockIdx.x;
    int bb = chan / DS, s = chan % DS;
    int t = threadIdx.x;
    __shared__ float sA[256], sB[256];
    float A = 1.0f, Bl = 0.0f;
    int base = bb * Lseq;
    #pragma unroll 4
    for (int i = 0; i < 16; i++) {
        size_t off = (size_t)(base + t * 16 + i) * DS + s;
        float a = expf(-g_dt[off]);
        Bl = a * Bl + g_bt[off];
        A = a * A;
    }
    sA[t] = A; sB[t] = Bl;
    __syncthreads();
    for (int offp = 1; offp < 256; offp <<= 1) {
        float pA = 0.f, pB = 0.f;
        bool has = (t >= offp);
        if (has) { pA = sA[t - offp]; pB = sB[t - offp]; }
        __syncthreads();
        if (has) { sB[t] = sA[t] * pB + sB[t]; sA[t] = sA[t] * pA; }
        __syncthreads();
    }
    float v = (t == 0) ? 0.0f : sB[t - 1];
    for (int i = 0; i < 16; i++) {
        size_t off = (size_t)(base + t * 16 + i) * DS + s;
        float a = expf(-g_dt[off]);
        v = a * v + g_bt[off];
        g_v[off] = v;
    }
}

// ======================= us + xs + us@W_us -> g_cat[:, :768] =================
__global__ __launch_bounds__(256) void us_y_kernel(const float* __restrict__ W_us,
                                                   const float* __restrict__ b_us) {
    int row = blockIdx.x, tid = threadIdx.x;
    int l = row % Lseq;
    float kf = (float)(Lseq - 1 - l);
    __shared__ float us_sh[DS];
    if (tid < DS) {
        size_t off = (size_t)row * DS + tid;
        float dt = g_dt[off], v = g_v[off], bt = g_bt[off];
        float denom = expm1f(-dt);
        if (denom > -1e-30f) denom = -1e-30f;
        us_sh[tid] = expf(-kf * dt) * v + bt * expm1f(-kf * dt) / denom;
    }
    __syncthreads();
    #pragma unroll
    for (int j = 0; j < 3; j++) {
        int d = tid + j * 256;
        float acc = g_xd[(size_t)row * NPACK + d] + b_us[d];
        #pragma unroll
        for (int s = 0; s < DS; s++)
            acc = fmaf(us_sh[s], W_us[s * DM + d], acc);
        g_cat[(size_t)row * EE + d] = acc;
    }
}

// ======================= launch =============================================
extern "C" void kernel_launch(void* const* d_in, const int* in_sizes, int n_in,
                              void* d_out, int out_size) {
    const float* x      = (const float*)d_in[0];
    const float* ln_g   = (const float*)d_in[1];
    const float* ln_b   = (const float*)d_in[2];
    const float* W_in   = (const float*)d_in[3];
    const float* b_in   = (const float*)d_in[4];
    const float* W_conv = (const float*)d_in[5];
    const float* b_conv = (const float*)d_in[6];
    const float* W_xp   = (const float*)d_in[7];
    const float* b_xp   = (const float*)d_in[8];
    const float* W_dt   = (const float*)d_in[9];
    const float* b_dt   = (const float*)d_in[10];
    const float* W_us   = (const float*)d_in[11];
    const float* b_us   = (const float*)d_in[12];
    const float* W_out  = (const float*)d_in[13];
    const float* b_out  = (const float*)d_in[14];
    float* out = (float*)d_out;

    float* xn   ; cudaGetSymbolAddress((void**)&xn,    g_xn);
    float* xin  ; cudaGetSymbolAddress((void**)&xin,   g_xin);
    float* xact ; cudaGetSymbolAddress((void**)&xact,  g_xact);
    float* cat  ; cudaGetSymbolAddress((void**)&cat,   g_cat);
    float* xd   ; cudaGetSymbolAddress((void**)&xd,    g_xd);
    float* wpack; cudaGetSymbolAddress((void**)&wpack, g_wpack);
    float* bpack; cudaGetSymbolAddress((void**)&bpack, g_bpack);
    float* winT ; cudaGetSymbolAddress((void**)&winT,  g_winT);
    float* wpT  ; cudaGetSymbolAddress((void**)&wpT,   g_wpackT);
    float* woutT; cudaGetSymbolAddress((void**)&woutT, g_woutT);

    const int GEMM_SMEM = STAGE_F * 2 * (int)sizeof(float);  // 73728
    cudaFuncSetAttribute(gemm_tf32_kernel,
                         cudaFuncAttributeMaxDynamicSharedMemorySize, GEMM_SMEM);
    dim3 tb(32, 8);

    // weight prep (independent of activations)
    transpose32<<<dim3(EE/32, DM/32), tb>>>(W_in, winT, DM, EE);            // -> [1536][768]
    pack_kernel<<<(EE * NPACK + 255) / 256, 256>>>(W_xp, b_xp, W_dt, b_dt);
    transpose32<<<dim3((NPACK+31)/32, EE/32), tb>>>(wpack, wpT, EE, NPACK); // -> [800][1536]
    transpose32<<<dim3(DM/32, EE/32), tb>>>(W_out, woutT, EE, DM);          // -> [768][1536]

    // 1. LayerNorm
    ln_kernel<<<NROWS, 256>>>(x, ln_g, ln_b);

    // 2. in-proj: xn(8192x768) @ W_in -> xin
    gemm_tf32_kernel<<<dim3(EE/128, NROWS/128), 256, GEMM_SMEM>>>(
        xn, DM, winT, EE, b_in, xin, EE, DM);

    // 3. conv + silu -> xact (+ upper half into g_cat)
    conv_silu_kernel<<<((NROWS/4) * EE + 255) / 256, 256>>>(b_conv, W_conv);

    // 4. packed proj: xact(8192x1536) @ [W_xp|W_dt] -> xd (800 cols)
    gemm_tf32_kernel<<<dim3((NPACK+127)/128, NROWS/128), 256, GEMM_SMEM>>>(
        xact, EE, wpT, NPACK, bpack, xd, NPACK, EE);

    // 5-7. scan pipeline
    prescan_kernel<<<(NROWS * DS + 255) / 256, 256>>>();
    scan_kernel<<<Bsz * DS, 256>>>();
    us_y_kernel<<<NROWS, 256>>>(W_us, b_us);

    // 8. out-proj: cat(8192x1536) @ W_out -> out
    gemm_tf32_kernel<<<dim3(DM/128, NROWS/128), 256, GEMM_SMEM>>>(
        cat, EE, woutT, DM, b_out, out, DM, EE);
}

// round 4
// speedup vs baseline: 3.4217x; 1.2590x over previous
#include <cuda_runtime.h>
#include <cstdint>
#include <math.h>

#define Bsz 2
#define Lseq 4096
#define DM 768
#define DS 16
#define EE 1536
#define NROWS (Bsz*Lseq)      // 8192
#define NPACK (DM + DS + DS)  // 800
#define NPAD 896              // NPACK padded to multiple of 128
#define LN_EPS 1e-5f

#define STAGES 3
#define AF_STAGE 4096         // floats per stage, A tile (128 rows x 32 k)
#define STAGE_FLOATS 8192     // A + B per stage

// ======================= small PTX helpers ==================================
__device__ __forceinline__ uint32_t smem_u32(const void* p) {
    uint32_t a;
    asm("{ .reg .u64 t; cvta.to.shared.u64 t, %1; cvt.u32.u64 %0, t; }"
        : "=r"(a) : "l"(p));
    return a;
}
__device__ __forceinline__ void cp_async16(uint32_t dst, const void* src) {
    asm volatile("cp.async.cg.shared.global [%0], [%1], 16;"
                 :: "r"(dst), "l"(src) : "memory");
}
__device__ __forceinline__ void cp_commit() {
    asm volatile("cp.async.commit_group;" ::: "memory");
}
template<int N> __device__ __forceinline__ void cp_wait() {
    asm volatile("cp.async.wait_group %0;" :: "n"(N) : "memory");
}
__device__ __forceinline__ uint32_t f2tf32(float x) {
    uint32_t r;
    asm("cvt.rna.tf32.f32 %0, %1;" : "=r"(r) : "f"(x));
    return r;
}
__device__ __forceinline__ float tfr(float x) { return __uint_as_float(f2tf32(x)); }
__device__ __forceinline__ void mma_tf32(float* c, const uint32_t* a, const uint32_t* b) {
    asm volatile("mma.sync.aligned.m16n8k8.row.col.f32.tf32.tf32.f32 "
        "{%0,%1,%2,%3}, {%4,%5,%6,%7}, {%8,%9}, {%0,%1,%2,%3};"
        : "+f"(c[0]), "+f"(c[1]), "+f"(c[2]), "+f"(c[3])
        : "r"(a[0]), "r"(a[1]), "r"(a[2]), "r"(a[3]), "r"(b[0]), "r"(b[1]));
}

// ---- fragment-native layout addressing -------------------------------------
// A panel-block: 16 rows x 8 k = 128 floats: [g:8][tg:4][quad:4]
//   quad order: {(g,k),(g+8,k),(g,k+4),(g+8,k+4)}
__device__ __forceinline__ size_t af_idx(int r, int k, int KC8) {
    return ((size_t)((r >> 4) * KC8 + (k >> 3))) * 128
         + (r & 7) * 16 + (k & 3) * 4 + ((r >> 3) & 1) + 2 * ((k >> 2) & 1);
}
// B n-group block: 8 n x 8 k = 64 floats: [g:8][tg:4][pair:2]
//   pair order: {(n,k),(n,k+4)}
__device__ __forceinline__ size_t bf_idx(int n, int k, int KC8) {
    return ((size_t)((n >> 3) * KC8 + (k >> 3))) * 64
         + (n & 7) * 8 + (k & 3) * 2 + ((k >> 2) & 1);
}

// ======================= scratch ============================================
__device__ float g_xn    [NROWS * DM];     // A_f for in-proj   (K=768)
__device__ float g_xin   [NROWS * EE];     // row-major
__device__ float g_xact  [NROWS * EE];     // A_f for packed    (K=1536)
__device__ float g_cat   [NROWS * EE];     // A_f for out-proj  (K=1536)
__device__ float g_xd    [NROWS * NPACK];  // row-major
__device__ float g_dt    [NROWS * DS];
__device__ float g_bt    [NROWS * DS];
__device__ float g_v     [NROWS * DS];
__device__ float g_bpack [NPACK];
__device__ float g_winF  [EE * DM];        // B_f: N=1536, K=768
__device__ float g_wpackF[NPAD * EE];      // B_f: N=896(pad), K=1536
__device__ float g_woutF [DM * EE];        // B_f: N=768, K=1536

// ======================= tf32 mma.sync GEMM =================================
// C[M, Ndim] = Af(M,K) @ Bf(N,K)^T + bias, fragment-native operand layouts.
// Block 128x128, K-chunk 32, 3-stage cp.async. 8 warps: wm=wid>>1 (32 rows),
// wn=wid&1 (64 cols).
__global__ __launch_bounds__(256, 2) void gemm_tf32_kernel(
    const float* __restrict__ Af, const float* __restrict__ Bf,
    const float* __restrict__ bias, float* __restrict__ C,
    int ldc, int Ndim, int K)
{
    extern __shared__ __align__(16) float sm[];
    const int tid = threadIdx.x;
    const int wid = tid >> 5, lane = tid & 31;
    const int wm = wid >> 1, wn = wid & 1;
    const int g = lane >> 2, tg = lane & 3;
    const int KC8 = K >> 3, NC = K >> 5;
    const int mp0 = blockIdx.y * 8;
    const int ng0 = blockIdx.x * 16;
    const int m0 = blockIdx.y * 128, n0 = blockIdx.x * 128;
    const uint32_t smb = smem_u32(sm);

    // loader: each thread copies 4x16B of A and 4x16B of B per chunk (contig)
    const int a_blk = tid >> 3;                    // 0..31 = mp*4+kc
    const float* a_src = Af + ((size_t)(mp0 + (a_blk >> 2)) * KC8 + (a_blk & 3)) * 128
                            + (tid & 7) * 16;
    const uint32_t a_dst = smb + (uint32_t)tid * 64u;

    const int b_blk = tid >> 2;                    // 0..63 = ng*4+kc
    const float* b_src = Bf + ((size_t)(ng0 + (b_blk >> 2)) * KC8 + (b_blk & 3)) * 64
                            + (tid & 3) * 16;
    const uint32_t b_dst = smb + AF_STAGE * 4u + (uint32_t)tid * 64u;

    auto load_chunk = [&](int c) {
        const uint32_t st = (uint32_t)(c % STAGES) * (STAGE_FLOATS * 4u);
        const float* ga = a_src + (size_t)c * 512;   // +4 kchunks of 128 floats
        const float* gb = b_src + (size_t)c * 256;   // +4 kchunks of 64 floats
        #pragma unroll
        for (int i = 0; i < 4; i++) {
            cp_async16(a_dst + st + i * 16u, ga + i * 4);
            cp_async16(b_dst + st + i * 16u, gb + i * 4);
        }
        cp_commit();
    };

    float acc[2][8][4];
    #pragma unroll
    for (int mi = 0; mi < 2; mi++)
        #pragma unroll
        for (int ni = 0; ni < 8; ni++)
            #pragma unroll
            for (int q = 0; q < 4; q++) acc[mi][ni][q] = 0.0f;

    load_chunk(0); load_chunk(1); load_chunk(2);

    for (int c = 0; c < NC; c++) {
        cp_wait<2>();
        __syncthreads();

        const float* as = sm + (c % STAGES) * STAGE_FLOATS
                        + (size_t)(wm * 2) * 512 + g * 16 + tg * 4;
        const float* bs = sm + (c % STAGES) * STAGE_FLOATS + AF_STAGE
                        + (size_t)(wn * 8) * 256 + g * 8 + tg * 2;

        #pragma unroll
        for (int kk = 0; kk < 4; kk++) {
            uint4 a0 = *(const uint4*)(as + kk * 128);
            uint4 a1 = *(const uint4*)(as + (4 + kk) * 128);
            uint2 bq[8];
            #pragma unroll
            for (int ni = 0; ni < 8; ni++)
                bq[ni] = *(const uint2*)(bs + (ni * 4 + kk) * 64);
            #pragma unroll
            for (int ni = 0; ni < 8; ni++) {
                mma_tf32(acc[0][ni], (const uint32_t*)&a0, (const uint32_t*)&bq[ni]);
                mma_tf32(acc[1][ni], (const uint32_t*)&a1, (const uint32_t*)&bq[ni]);
            }
        }

        __syncthreads();
        if (c + 3 < NC) load_chunk(c + 3); else cp_commit();
    }

    // epilogue: registers -> row-major C (+bias)
    #pragma unroll
    for (int mi = 0; mi < 2; mi++) {
        const int row = m0 + wm * 32 + mi * 16 + g;
        float* c0 = C + (size_t)row * ldc;
        float* c1 = C + (size_t)(row + 8) * ldc;
        #pragma unroll
        for (int ni = 0; ni < 8; ni++) {
            const int col = n0 + wn * 64 + ni * 8 + tg * 2;
            if (col < Ndim) {
                float bx = bias[col], by = bias[col + 1];
                *(float2*)(c0 + col) = make_float2(acc[mi][ni][0] + bx, acc[mi][ni][1] + by);
                *(float2*)(c1 + col) = make_float2(acc[mi][ni][2] + bx, acc[mi][ni][3] + by);
            }
        }
    }
}

// ======================= LayerNorm -> A_f(K=768), pre-rounded ===============
__global__ __launch_bounds__(256) void ln_kernel(const float* __restrict__ x,
                                                 const float* __restrict__ g,
                                                 const float* __restrict__ b) {
    int row = blockIdx.x, tid = threadIdx.x;
    const float* xr = x + (size_t)row * DM;
    float v0 = xr[tid], v1 = xr[tid + 256], v2 = xr[tid + 512];
    __shared__ float red[256];
    red[tid] = v0 + v1 + v2; __syncthreads();
    for (int off = 128; off > 0; off >>= 1) {
        if (tid < off) red[tid] += red[tid + off];
        __syncthreads();
    }
    float mu = red[0] * (1.0f / DM); __syncthreads();
    float d0 = v0 - mu, d1 = v1 - mu, d2 = v2 - mu;
    red[tid] = d0*d0 + d1*d1 + d2*d2; __syncthreads();
    for (int off = 128; off > 0; off >>= 1) {
        if (tid < off) red[tid] += red[tid + off];
        __syncthreads();
    }
    float rstd = rsqrtf(red[0] * (1.0f / DM) + LN_EPS);
    g_xn[af_idx(row, tid,       96)] = tfr(d0 * rstd * g[tid]       + b[tid]);
    g_xn[af_idx(row, tid + 256, 96)] = tfr(d1 * rstd * g[tid + 256] + b[tid + 256]);
    g_xn[af_idx(row, tid + 512, 96)] = tfr(d2 * rstd * g[tid + 512] + b[tid + 512]);
}

// ======================= weight format kernels ==============================
// Generic: W row-major [K][N] -> B_f(N, K), pre-rounded.
__global__ void bfmt_kernel(const float* __restrict__ W, float* __restrict__ Bf,
                            int N, int KC8) {
    int idx = blockIdx.x * blockDim.x + threadIdx.x;
    int k = idx / N, n = idx % N;
    Bf[bf_idx(n, k, KC8)] = tfr(W[idx]);
}

// Packed [W_xp | W_dt | zero-pad] -> B_f(N=896, K=1536)
__global__ void bfmt_pack_kernel(const float* __restrict__ W_xp,
                                 const float* __restrict__ W_dt) {
    int idx = blockIdx.x * blockDim.x + threadIdx.x;
    if (idx >= NPAD * EE) return;
    int k = idx / NPAD, n = idx % NPAD;
    float v = (n < DM + DS) ? W_xp[k * (DM + DS) + n]
            : (n < NPACK)   ? W_dt[k * DS + (n - (DM + DS))]
            : 0.0f;
    g_wpackF[bf_idx(n, k, 192)] = tfr(v);
}

__global__ void bias_pack_kernel(const float* __restrict__ b_xp,
                                 const float* __restrict__ b_dt) {
    int idx = blockIdx.x * blockDim.x + threadIdx.x;
    if (idx < NPACK)
        g_bpack[idx] = (idx < DM + DS) ? b_xp[idx] : b_dt[idx - (DM + DS)];
}

// ======================= depthwise conv (k=4) + SiLU -> A_f(K=1536) =========
__global__ void conv_silu_kernel(const float* __restrict__ b_conv,
                                 const float* __restrict__ W_conv) {
    int idx = blockIdx.x * blockDim.x + threadIdx.x;
    if (idx >= (NROWS / 4) * EE) return;
    int e = idx % EE;
    int r0 = (idx / EE) * 4;
    int l0 = r0 % Lseq;
    const float4 w = *(const float4*)(W_conv + e * 4);
    float bc = b_conv[e];
    float x0 = (l0 >= 3) ? g_xin[(size_t)(r0 - 3) * EE + e] : 0.f;
    float x1 = (l0 >= 2) ? g_xin[(size_t)(r0 - 2) * EE + e] : 0.f;
    float x2 = (l0 >= 1) ? g_xin[(size_t)(r0 - 1) * EE + e] : 0.f;
    float x3 = g_xin[(size_t)(r0 + 0) * EE + e];
    float x4 = g_xin[(size_t)(r0 + 1) * EE + e];
    float x5 = g_xin[(size_t)(r0 + 2) * EE + e];
    float x6 = g_xin[(size_t)(r0 + 3) * EE + e];
    float s0 = bc + x0 * w.x + x1 * w.y + x2 * w.z + x3 * w.w;
    float s1 = bc + x1 * w.x + x2 * w.y + x3 * w.z + x4 * w.w;
    float s2 = bc + x2 * w.x + x3 * w.y + x4 * w.z + x5 * w.w;
    float s3 = bc + x3 * w.x + x4 * w.y + x5 * w.z + x6 * w.w;
    float a0 = tfr(s0 / (1.0f + expf(-s0)));
    float a1 = tfr(s1 / (1.0f + expf(-s1)));
    float a2 = tfr(s2 / (1.0f + expf(-s2)));
    float a3 = tfr(s3 / (1.0f + expf(-s3)));
    g_xact[af_idx(r0 + 0, e, 192)] = a0;
    g_xact[af_idx(r0 + 1, e, 192)] = a1;
    g_xact[af_idx(r0 + 2, e, 192)] = a2;
    g_xact[af_idx(r0 + 3, e, 192)] = a3;
    if (e >= DM) {
        g_cat[af_idx(r0 + 0, e, 192)] = a0;
        g_cat[af_idx(r0 + 1, e, 192)] = a1;
        g_cat[af_idx(r0 + 2, e, 192)] = a2;
        g_cat[af_idx(r0 + 3, e, 192)] = a3;
    }
}

// ======================= pre-scan elementwise ================================
__global__ void prescan_kernel() {
    int idx = blockIdx.x * blockDim.x + threadIdx.x;
    if (idx >= NROWS * DS) return;
    int row = idx / DS, s = idx % DS;
    float dtraw = g_xd[(size_t)row * NPACK + (DM + DS) + s];
    float ds    = g_xd[(size_t)row * NPACK + DM + s];
    float dt = fmaxf(dtraw, 0.0f) + log1pf(expf(-fabsf(dtraw)));
    g_dt[idx] = dt;
    g_bt[idx] = ds * expf(-0.5f * dt);
}

// ======================= parallel scan ======================================
__global__ __launch_bounds__(256) void scan_kernel() {
    int chan = blockIdx.x;
    int bb = chan / DS, s = chan % DS;
    int t = threadIdx.x;
    __shared__ float sA[256], sB[256];
    float A = 1.0f, Bl = 0.0f;
    int base = bb * Lseq;
    #pragma unroll 4
    for (int i = 0; i < 16; i++) {
        size_t off = (size_t)(base + t * 16 + i) * DS + s;
        float a = expf(-g_dt[off]);
        Bl = a * Bl + g_bt[off];
        A = a * A;
    }
    sA[t] = A; sB[t] = Bl;
    __syncthreads();
    for (int offp = 1; offp < 256; offp <<= 1) {
        float pA = 0.f, pB = 0.f;
        bool has = (t >= offp);
        if (has) { pA = sA[t - offp]; pB = sB[t - offp]; }
        __syncthreads();
        if (has) { sB[t] = sA[t] * pB + sB[t]; sA[t] = sA[t] * pA; }
        __syncthreads();
    }
    float v = (t == 0) ? 0.0f : sB[t - 1];
    for (int i = 0; i < 16; i++) {
        size_t off = (size_t)(base + t * 16 + i) * DS + s;
        float a = expf(-g_dt[off]);
        v = a * v + g_bt[off];
        g_v[off] = v;
    }
}

// ======================= us + xs + us@W_us -> g_cat A_f(K=1536) =============
__global__ __launch_bounds__(256) void us_y_kernel(const float* __restrict__ W_us,
                                                   const float* __restrict__ b_us) {
    int row = blockIdx.x, tid = threadIdx.x;
    int l = row % Lseq;
    float kf = (float)(Lseq - 1 - l);
    __shared__ float us_sh[DS];
    if (tid < DS) {
        size_t off = (size_t)row * DS + tid;
        float dt = g_dt[off], v = g_v[off], bt = g_bt[off];
        float denom = expm1f(-dt);
        if (denom > -1e-30f) denom = -1e-30f;
        us_sh[tid] = expf(-kf * dt) * v + bt * expm1f(-kf * dt) / denom;
    }
    __syncthreads();
    #pragma unroll
    for (int j = 0; j < 3; j++) {
        int d = tid + j * 256;
        float acc = g_xd[(size_t)row * NPACK + d] + b_us[d];
        #pragma unroll
        for (int s = 0; s < DS; s++)
            acc = fmaf(us_sh[s], W_us[s * DM + d], acc);
        g_cat[af_idx(row, d, 192)] = tfr(acc);
    }
}

// ======================= launch =============================================
extern "C" void kernel_launch(void* const* d_in, const int* in_sizes, int n_in,
                              void* d_out, int out_size) {
    const float* x      = (const float*)d_in[0];
    const float* ln_g   = (const float*)d_in[1];
    const float* ln_b   = (const float*)d_in[2];
    const float* W_in   = (const float*)d_in[3];
    const float* b_in   = (const float*)d_in[4];
    const float* W_conv = (const float*)d_in[5];
    const float* b_conv = (const float*)d_in[6];
    const float* W_xp   = (const float*)d_in[7];
    const float* b_xp   = (const float*)d_in[8];
    const float* W_dt   = (const float*)d_in[9];
    const float* b_dt   = (const float*)d_in[10];
    const float* W_us   = (const float*)d_in[11];
    const float* b_us   = (const float*)d_in[12];
    const float* W_out  = (const float*)d_in[13];
    const float* b_out  = (const float*)d_in[14];
    float* out = (float*)d_out;

    float* xn   ; cudaGetSymbolAddress((void**)&xn,    g_xn);
    float* xin  ; cudaGetSymbolAddress((void**)&xin,   g_xin);
    float* xact ; cudaGetSymbolAddress((void**)&xact,  g_xact);
    float* cat  ; cudaGetSymbolAddress((void**)&cat,   g_cat);
    float* xd   ; cudaGetSymbolAddress((void**)&xd,    g_xd);
    float* bpack; cudaGetSymbolAddress((void**)&bpack, g_bpack);
    float* winF ; cudaGetSymbolAddress((void**)&winF,  g_winF);
    float* wpF  ; cudaGetSymbolAddress((void**)&wpF,   g_wpackF);
    float* woutF; cudaGetSymbolAddress((void**)&woutF, g_woutF);

    const int GEMM_SMEM = STAGES * STAGE_FLOATS * (int)sizeof(float);  // 98304
    cudaFuncSetAttribute(gemm_tf32_kernel,
                         cudaFuncAttributeMaxDynamicSharedMemorySize, GEMM_SMEM);

    // weight formatting (independent of activations)
    bfmt_kernel<<<(EE * DM) / 256, 256>>>(W_in, winF, EE, 96);    // N=1536, K=768
    bfmt_kernel<<<(DM * EE) / 256, 256>>>(W_out, woutF, DM, 192); // N=768,  K=1536
    bfmt_pack_kernel<<<(NPAD * EE + 255) / 256, 256>>>(W_xp, W_dt);
    bias_pack_kernel<<<4, 256>>>(b_xp, b_dt);

    // 1. LayerNorm -> A_f
    ln_kernel<<<NROWS, 256>>>(x, ln_g, ln_b);

    // 2. in-proj: (8192x768) @ (768x1536) -> xin (row-major)
    gemm_tf32_kernel<<<dim3(EE/128, NROWS/128), 256, GEMM_SMEM>>>(
        xn, winF, b_in, xin, EE, EE, DM);

    // 3. conv + silu -> xact A_f (+ upper half into g_cat A_f)
    conv_silu_kernel<<<((NROWS/4) * EE + 255) / 256, 256>>>(b_conv, W_conv);

    // 4. packed proj: (8192x1536) @ (1536x800) -> xd (row-major)
    gemm_tf32_kernel<<<dim3(NPAD/128, NROWS/128), 256, GEMM_SMEM>>>(
        xact, wpF, bpack, xd, NPACK, NPACK, EE);

    // 5-7. scan pipeline
    prescan_kernel<<<(NROWS * DS + 255) / 256, 256>>>();
    scan_kernel<<<Bsz * DS, 256>>>();
    us_y_kernel<<<NROWS, 256>>>(W_us, b_us);

    // 8. out-proj: (8192x1536) @ (1536x768) -> out
    gemm_tf32_kernel<<<dim3(DM/128, NROWS/128), 256, GEMM_SMEM>>>(
        cat, woutF, b_out, out, DM, DM, EE);
}

// round 5
// speedup vs baseline: 6.4587x; 1.8876x over previous
#include <cuda_runtime.h>
#include <cuda_fp16.h>
#include <cstdint>
#include <math.h>

#define Bsz 2
#define Lseq 4096
#define DM 768
#define DS 16
#define EE 1536
#define NROWS (Bsz*Lseq)      // 8192
#define NPACK (DM + DS + DS)  // 800
#define NPAD 896              // NPACK padded to multiple of 128
#define LN_EPS 1e-5f

#define STAGES 4
#define STAGE_BYTES 16384     // A tile (8192 B) + B tile (8192 B), fp16

// ======================= small PTX helpers ==================================
__device__ __forceinline__ uint32_t smem_u32(const void* p) {
    uint32_t a;
    asm("{ .reg .u64 t; cvta.to.shared.u64 t, %1; cvt.u32.u64 %0, t; }"
        : "=r"(a) : "l"(p));
    return a;
}
__device__ __forceinline__ void cp_async16(uint32_t dst, const void* src) {
    asm volatile("cp.async.cg.shared.global [%0], [%1], 16;"
                 :: "r"(dst), "l"(src) : "memory");
}
__device__ __forceinline__ void cp_commit() {
    asm volatile("cp.async.commit_group;" ::: "memory");
}
template<int N> __device__ __forceinline__ void cp_wait() {
    asm volatile("cp.async.wait_group %0;" :: "n"(N) : "memory");
}
__device__ __forceinline__ void mma_f16(float* c, const uint32_t* a, const uint32_t* b) {
    asm volatile("mma.sync.aligned.m16n8k16.row.col.f32.f16.f16.f32 "
        "{%0,%1,%2,%3}, {%4,%5,%6,%7}, {%8,%9}, {%0,%1,%2,%3};"
        : "+f"(c[0]), "+f"(c[1]), "+f"(c[2]), "+f"(c[3])
        : "r"(a[0]), "r"(a[1]), "r"(a[2]), "r"(a[3]), "r"(b[0]), "r"(b[1]));
}

// ---- fp16 fragment-native layout addressing (half-element index) -----------
// A block: 16 rows x 16 k = 256 halfs. b32 quad per (g,tg):
//   {(g,2tg),(g+8,2tg),(g,2tg+8),(g+8,2tg+8)}
__device__ __forceinline__ size_t afh_idx(int r, int k, int KC16) {
    size_t blk = (size_t)((r >> 4) * KC16 + (k >> 4));
    int b32 = (r & 7) * 16 + ((k >> 1) & 3) * 4 + ((r >> 3) & 1) + 2 * ((k >> 3) & 1);
    return blk * 256 + b32 * 2 + (k & 1);
}
// B block: 8 n x 16 k = 128 halfs. b32 pair per (g,tg): {(n=g,2tg),(n=g,2tg+8)}
__device__ __forceinline__ size_t bfh_idx(int n, int k, int KC16) {
    size_t blk = (size_t)((n >> 3) * KC16 + (k >> 4));
    int b32 = (n & 7) * 8 + ((k >> 1) & 3) * 2 + ((k >> 3) & 1);
    return blk * 128 + b32 * 2 + (k & 1);
}

// ======================= scratch ============================================
__device__ __align__(256) __half g_xn    [NROWS * DM];   // A_f in-proj  (K=768)
__device__ __align__(256) float  g_xin   [NROWS * EE];   // row-major fp32
__device__ __align__(256) __half g_xact  [NROWS * EE];   // A_f packed   (K=1536)
__device__ __align__(256) __half g_cat   [NROWS * EE];   // A_f out-proj (K=1536)
__device__ __align__(256) float  g_xd    [NROWS * NPACK];
__device__ float g_dt [NROWS * DS];
__device__ float g_bt [NROWS * DS];
__device__ float g_v  [NROWS * DS];
__device__ float g_bpack[NPACK];
__device__ __align__(256) __half g_winF  [EE * DM];      // B_f: N=1536, K=768
__device__ __align__(256) __half g_wpackF[NPAD * EE];    // B_f: N=896,  K=1536
__device__ __align__(256) __half g_woutF [DM * EE];      // B_f: N=768,  K=1536

// ======================= fp16 mma.sync GEMM =================================
// C[M, Ndim] = Af(M,K) @ Bf(N,K)^T + bias (fp32 accum/output).
// Block 128x128, K-chunk 32, 4-stage cp.async. 8 warps: wm=wid>>1, wn=wid&1.
__global__ __launch_bounds__(256, 2) void gemm_f16_kernel(
    const __half* __restrict__ Af, const __half* __restrict__ Bf,
    const float* __restrict__ bias, float* __restrict__ C,
    int ldc, int Ndim, int K)
{
    extern __shared__ __align__(16) char sm[];
    const int tid = threadIdx.x;
    const int wid = tid >> 5, lane = tid & 31;
    const int wm = wid >> 1, wn = wid & 1;
    const int g = lane >> 2, tg = lane & 3;
    const int KC16 = K >> 4, NC = K >> 5;
    const int mp0 = blockIdx.y * 8;     // first 16-row A panel
    const int ng0 = blockIdx.x * 16;    // first 8-col B group
    const int m0 = blockIdx.y * 128, n0 = blockIdx.x * 128;
    const uint32_t smb = smem_u32(sm);

    // ---- loaders: 2 A lines + 2 B lines of 16B per thread per chunk --------
    const __half* a_src0 = Af + ((size_t)(mp0 + (tid >> 6)) * KC16) * 256 + (tid & 63) * 8;
    const __half* a_src1 = Af + ((size_t)(mp0 + (tid >> 6) + 4) * KC16) * 256 + (tid & 63) * 8;
    const __half* b_src0 = Bf + ((size_t)(ng0 + (tid >> 5)) * KC16) * 128 + (tid & 31) * 8;
    const __half* b_src1 = Bf + ((size_t)(ng0 + (tid >> 5) + 8) * KC16) * 128 + (tid & 31) * 8;
    const uint32_t a_dst0 = smb + (uint32_t)tid * 16u;
    const uint32_t a_dst1 = smb + (uint32_t)(tid + 256) * 16u;
    const uint32_t b_dst0 = smb + 8192u + (uint32_t)tid * 16u;
    const uint32_t b_dst1 = smb + 8192u + (uint32_t)(tid + 256) * 16u;

    auto load_chunk = [&](int c) {
        const uint32_t st = (uint32_t)(c & 3) * STAGE_BYTES;
        cp_async16(a_dst0 + st, a_src0 + (size_t)c * 512);  // 2 k-blocks x 256 halfs
        cp_async16(a_dst1 + st, a_src1 + (size_t)c * 512);
        cp_async16(b_dst0 + st, b_src0 + (size_t)c * 256);  // 2 k-blocks x 128 halfs
        cp_async16(b_dst1 + st, b_src1 + (size_t)c * 256);
        cp_commit();
    };

    float acc[2][8][4];
    #pragma unroll
    for (int mi = 0; mi < 2; mi++)
        #pragma unroll
        for (int ni = 0; ni < 8; ni++)
            #pragma unroll
            for (int q = 0; q < 4; q++) acc[mi][ni][q] = 0.0f;

    load_chunk(0); load_chunk(1); load_chunk(2);

    const char* stA_base = sm + wm * 2048 + g * 64 + tg * 16;
    const char* stB_base = sm + 8192 + wn * 4096 + g * 32 + tg * 8;

    for (int c = 0; c < NC; c++) {
        cp_wait<2>();
        __syncthreads();

        const char* stA = stA_base + (c & 3) * STAGE_BYTES;
        const char* stB = stB_base + (c & 3) * STAGE_BYTES;

        #pragma unroll
        for (int kb = 0; kb < 2; kb++) {
            uint4 a0 = *(const uint4*)(stA + kb * 512);
            uint4 a1 = *(const uint4*)(stA + 1024 + kb * 512);
            uint2 bq[8];
            #pragma unroll
            for (int ni = 0; ni < 8; ni++)
                bq[ni] = *(const uint2*)(stB + ni * 512 + kb * 256);
            #pragma unroll
            for (int ni = 0; ni < 8; ni++) {
                mma_f16(acc[0][ni], (const uint32_t*)&a0, (const uint32_t*)&bq[ni]);
                mma_f16(acc[1][ni], (const uint32_t*)&a1, (const uint32_t*)&bq[ni]);
            }
        }

        __syncthreads();
        if (c + 3 < NC) load_chunk(c + 3); else cp_commit();
    }

    // ---- epilogue: registers -> row-major fp32 C (+bias) --------------------
    #pragma unroll
    for (int mi = 0; mi < 2; mi++) {
        const int row = m0 + wm * 32 + mi * 16 + g;
        float* c0 = C + (size_t)row * ldc;
        float* c1 = C + (size_t)(row + 8) * ldc;
        #pragma unroll
        for (int ni = 0; ni < 8; ni++) {
            const int col = n0 + wn * 64 + ni * 8 + tg * 2;
            if (col < Ndim) {
                float bx = bias[col], by = bias[col + 1];
                *(float2*)(c0 + col) = make_float2(acc[mi][ni][0] + bx, acc[mi][ni][1] + by);
                *(float2*)(c1 + col) = make_float2(acc[mi][ni][2] + bx, acc[mi][ni][3] + by);
            }
        }
    }
}

// ======================= LayerNorm -> A_f fp16 (K=768) ======================
__global__ __launch_bounds__(256) void ln_kernel(const float* __restrict__ x,
                                                 const float* __restrict__ g,
                                                 const float* __restrict__ b) {
    int row = blockIdx.x, tid = threadIdx.x;
    const float* xr = x + (size_t)row * DM;
    float v0 = xr[tid], v1 = xr[tid + 256], v2 = xr[tid + 512];
    __shared__ float red[256];
    red[tid] = v0 + v1 + v2; __syncthreads();
    for (int off = 128; off > 0; off >>= 1) {
        if (tid < off) red[tid] += red[tid + off];
        __syncthreads();
    }
    float mu = red[0] * (1.0f / DM); __syncthreads();
    float d0 = v0 - mu, d1 = v1 - mu, d2 = v2 - mu;
    red[tid] = d0*d0 + d1*d1 + d2*d2; __syncthreads();
    for (int off = 128; off > 0; off >>= 1) {
        if (tid < off) red[tid] += red[tid + off];
        __syncthreads();
    }
    float rstd = rsqrtf(red[0] * (1.0f / DM) + LN_EPS);
    g_xn[afh_idx(row, tid,       48)] = __float2half_rn(d0 * rstd * g[tid]       + b[tid]);
    g_xn[afh_idx(row, tid + 256, 48)] = __float2half_rn(d1 * rstd * g[tid + 256] + b[tid + 256]);
    g_xn[afh_idx(row, tid + 512, 48)] = __float2half_rn(d2 * rstd * g[tid + 512] + b[tid + 512]);
}

// ======================= weight format kernels ==============================
__global__ void bfmt_kernel(const float* __restrict__ W, __half* __restrict__ Bf,
                            int N, int KC16) {  // W row-major [K][N]
    int idx = blockIdx.x * blockDim.x + threadIdx.x;
    int k = idx / N, n = idx % N;
    Bf[bfh_idx(n, k, KC16)] = __float2half_rn(W[idx]);
}

__global__ void bfmt_pack_kernel(const float* __restrict__ W_xp,
                                 const float* __restrict__ W_dt) {
    int idx = blockIdx.x * blockDim.x + threadIdx.x;
    if (idx >= NPAD * EE) return;
    int k = idx / NPAD, n = idx % NPAD;
    float v = (n < DM + DS) ? W_xp[k * (DM + DS) + n]
            : (n < NPACK)   ? W_dt[k * DS + (n - (DM + DS))]
            : 0.0f;
    g_wpackF[bfh_idx(n, k, 96)] = __float2half_rn(v);
}

__global__ void bias_pack_kernel(const float* __restrict__ b_xp,
                                 const float* __restrict__ b_dt) {
    int idx = blockIdx.x * blockDim.x + threadIdx.x;
    if (idx < NPACK)
        g_bpack[idx] = (idx < DM + DS) ? b_xp[idx] : b_dt[idx - (DM + DS)];
}

// ======================= depthwise conv (k=4) + SiLU -> A_f fp16 ============
__global__ void conv_silu_kernel(const float* __restrict__ b_conv,
                                 const float* __restrict__ W_conv) {
    int idx = blockIdx.x * blockDim.x + threadIdx.x;
    if (idx >= (NROWS / 4) * EE) return;
    int e = idx % EE;
    int r0 = (idx / EE) * 4;
    int l0 = r0 % Lseq;
    const float4 w = *(const float4*)(W_conv + e * 4);
    float bc = b_conv[e];
    float x0 = (l0 >= 3) ? g_xin[(size_t)(r0 - 3) * EE + e] : 0.f;
    float x1 = (l0 >= 2) ? g_xin[(size_t)(r0 - 2) * EE + e] : 0.f;
    float x2 = (l0 >= 1) ? g_xin[(size_t)(r0 - 1) * EE + e] : 0.f;
    float x3 = g_xin[(size_t)(r0 + 0) * EE + e];
    float x4 = g_xin[(size_t)(r0 + 1) * EE + e];
    float x5 = g_xin[(size_t)(r0 + 2) * EE + e];
    float x6 = g_xin[(size_t)(r0 + 3) * EE + e];
    float s0 = bc + x0 * w.x + x1 * w.y + x2 * w.z + x3 * w.w;
    float s1 = bc + x1 * w.x + x2 * w.y + x3 * w.z + x4 * w.w;
    float s2 = bc + x2 * w.x + x3 * w.y + x4 * w.z + x5 * w.w;
    float s3 = bc + x3 * w.x + x4 * w.y + x5 * w.z + x6 * w.w;
    __half a0 = __float2half_rn(s0 / (1.0f + expf(-s0)));
    __half a1 = __float2half_rn(s1 / (1.0f + expf(-s1)));
    __half a2 = __float2half_rn(s2 / (1.0f + expf(-s2)));
    __half a3 = __float2half_rn(s3 / (1.0f + expf(-s3)));
    g_xact[afh_idx(r0 + 0, e, 96)] = a0;
    g_xact[afh_idx(r0 + 1, e, 96)] = a1;
    g_xact[afh_idx(r0 + 2, e, 96)] = a2;
    g_xact[afh_idx(r0 + 3, e, 96)] = a3;
    if (e >= DM) {
        g_cat[afh_idx(r0 + 0, e, 96)] = a0;
        g_cat[afh_idx(r0 + 1, e, 96)] = a1;
        g_cat[afh_idx(r0 + 2, e, 96)] = a2;
        g_cat[afh_idx(r0 + 3, e, 96)] = a3;
    }
}

// ======================= pre-scan elementwise ================================
__global__ void prescan_kernel() {
    int idx = blockIdx.x * blockDim.x + threadIdx.x;
    if (idx >= NROWS * DS) return;
    int row = idx / DS, s = idx % DS;
    float dtraw = g_xd[(size_t)row * NPACK + (DM + DS) + s];
    float ds    = g_xd[(size_t)row * NPACK + DM + s];
    float dt = fmaxf(dtraw, 0.0f) + log1pf(expf(-fabsf(dtraw)));
    g_dt[idx] = dt;
    g_bt[idx] = ds * expf(-0.5f * dt);
}

// ======================= parallel scan ======================================
__global__ __launch_bounds__(256) void scan_kernel() {
    int chan = blockIdx.x;
    int bb = chan / DS, s = chan % DS;
    int t = threadIdx.x;
    __shared__ float sA[256], sB[256];
    float A = 1.0f, Bl = 0.0f;
    int base = bb * Lseq;
    #pragma unroll 4
    for (int i = 0; i < 16; i++) {
        size_t off = (size_t)(base + t * 16 + i) * DS + s;
        float a = expf(-g_dt[off]);
        Bl = a * Bl + g_bt[off];
        A = a * A;
    }
    sA[t] = A; sB[t] = Bl;
    __syncthreads();
    for (int offp = 1; offp < 256; offp <<= 1) {
        float pA = 0.f, pB = 0.f;
        bool has = (t >= offp);
        if (has) { pA = sA[t - offp]; pB = sB[t - offp]; }
        __syncthreads();
        if (has) { sB[t] = sA[t] * pB + sB[t]; sA[t] = sA[t] * pA; }
        __syncthreads();
    }
    float v = (t == 0) ? 0.0f : sB[t - 1];
    for (int i = 0; i < 16; i++) {
        size_t off = (size_t)(base + t * 16 + i) * DS + s;
        float a = expf(-g_dt[off]);
        v = a * v + g_bt[off];
        g_v[off] = v;
    }
}

// ======================= us + xs + us@W_us -> g_cat fp16 (K=1536) ===========
__global__ __launch_bounds__(256) void us_y_kernel(const float* __restrict__ W_us,
                                                   const float* __restrict__ b_us) {
    int row = blockIdx.x, tid = threadIdx.x;
    int l = row % Lseq;
    float kf = (float)(Lseq - 1 - l);
    __shared__ float us_sh[DS];
    if (tid < DS) {
        size_t off = (size_t)row * DS + tid;
        float dt = g_dt[off], v = g_v[off], bt = g_bt[off];
        float denom = expm1f(-dt);
        if (denom > -1e-30f) denom = -1e-30f;
        us_sh[tid] = expf(-kf * dt) * v + bt * expm1f(-kf * dt) / denom;
    }
    __syncthreads();
    #pragma unroll
    for (int j = 0; j < 3; j++) {
        int d = tid + j * 256;
        float acc = g_xd[(size_t)row * NPACK + d] + b_us[d];
        #pragma unroll
        for (int s = 0; s < DS; s++)
            acc = fmaf(us_sh[s], W_us[s * DM + d], acc);
        g_cat[afh_idx(row, d, 96)] = __float2half_rn(acc);
    }
}

// ======================= launch =============================================
extern "C" void kernel_launch(void* const* d_in, const int* in_sizes, int n_in,
                              void* d_out, int out_size) {
    const float* x      = (const float*)d_in[0];
    const float* ln_g   = (const float*)d_in[1];
    const float* ln_b   = (const float*)d_in[2];
    const float* W_in   = (const float*)d_in[3];
    const float* b_in   = (const float*)d_in[4];
    const float* W_conv = (const float*)d_in[5];
    const float* b_conv = (const float*)d_in[6];
    const float* W_xp   = (const float*)d_in[7];
    const float* b_xp   = (const float*)d_in[8];
    const float* W_dt   = (const float*)d_in[9];
    const float* b_dt   = (const float*)d_in[10];
    const float* W_us   = (const float*)d_in[11];
    const float* b_us   = (const float*)d_in[12];
    const float* W_out  = (const float*)d_in[13];
    const float* b_out  = (const float*)d_in[14];
    float* out = (float*)d_out;

    __half* xn  ; cudaGetSymbolAddress((void**)&xn,    g_xn);
    float*  xin ; cudaGetSymbolAddress((void**)&xin,   g_xin);
    __half* xact; cudaGetSymbolAddress((void**)&xact,  g_xact);
    __half* cat ; cudaGetSymbolAddress((void**)&cat,   g_cat);
    float*  xd  ; cudaGetSymbolAddress((void**)&xd,    g_xd);
    float* bpack; cudaGetSymbolAddress((void**)&bpack, g_bpack);
    __half* winF ; cudaGetSymbolAddress((void**)&winF,  g_winF);
    __half* wpF  ; cudaGetSymbolAddress((void**)&wpF,   g_wpackF);
    __half* woutF; cudaGetSymbolAddress((void**)&woutF, g_woutF);

    const int GEMM_SMEM = STAGES * STAGE_BYTES;  // 65536
    cudaFuncSetAttribute(gemm_f16_kernel,
                         cudaFuncAttributeMaxDynamicSharedMemorySize, GEMM_SMEM);

    // weight formatting (independent of activations)
    bfmt_kernel<<<(EE * DM) / 256, 256>>>(W_in, winF, EE, 48);    // N=1536, K=768
    bfmt_kernel<<<(DM * EE) / 256, 256>>>(W_out, woutF, DM, 96);  // N=768,  K=1536
    bfmt_pack_kernel<<<(NPAD * EE + 255) / 256, 256>>>(W_xp, W_dt);
    bias_pack_kernel<<<4, 256>>>(b_xp, b_dt);

    // 1. LayerNorm -> A_f
    ln_kernel<<<NROWS, 256>>>(x, ln_g, ln_b);

    // 2. in-proj: (8192x768) @ (768x1536) -> xin (fp32 row-major)
    gemm_f16_kernel<<<dim3(EE/128, NROWS/128), 256, GEMM_SMEM>>>(
        xn, winF, b_in, xin, EE, EE, DM);

    // 3. conv + silu -> xact A_f (+ upper half into g_cat A_f)
    conv_silu_kernel<<<((NROWS/4) * EE + 255) / 256, 256>>>(b_conv, W_conv);

    // 4. packed proj: (8192x1536) @ (1536x800) -> xd (fp32 row-major)
    gemm_f16_kernel<<<dim3(NPAD/128, NROWS/128), 256, GEMM_SMEM>>>(
        xact, wpF, bpack, xd, NPACK, NPACK, EE);

    // 5-7. scan pipeline
    prescan_kernel<<<(NROWS * DS + 255) / 256, 256>>>();
    scan_kernel<<<Bsz * DS, 256>>>();
    us_y_kernel<<<NROWS, 256>>>(W_us, b_us);

    // 8. out-proj: (8192x1536) @ (1536x768) -> out
    gemm_f16_kernel<<<dim3(DM/128, NROWS/128), 256, GEMM_SMEM>>>(
        cat, woutF, b_out, out, DM, DM, EE);
}

// round 6
// speedup vs baseline: 6.4682x; 1.0015x over previous
#include <cuda_runtime.h>
#include <cuda_fp16.h>
#include <cstdint>
#include <math.h>

#define Bsz 2
#define Lseq 4096
#define DM 768
#define DS 16
#define EE 1536
#define NROWS (Bsz*Lseq)      // 8192
#define NPACK (DM + DS + DS)  // 800
#define NPAD 896              // NPACK padded to multiple of 128
#define LN_EPS 1e-5f

#define STAGES 4
#define STAGE_BYTES 16384     // A tile (8192 B) + B tile (8192 B), fp16

// ======================= small PTX helpers ==================================
__device__ __forceinline__ uint32_t smem_u32(const void* p) {
    uint32_t a;
    asm("{ .reg .u64 t; cvta.to.shared.u64 t, %1; cvt.u32.u64 %0, t; }"
        : "=r"(a) : "l"(p));
    return a;
}
__device__ __forceinline__ void cp_async16(uint32_t dst, const void* src) {
    asm volatile("cp.async.cg.shared.global [%0], [%1], 16;"
                 :: "r"(dst), "l"(src) : "memory");
}
__device__ __forceinline__ void cp_commit() {
    asm volatile("cp.async.commit_group;" ::: "memory");
}
template<int N> __device__ __forceinline__ void cp_wait() {
    asm volatile("cp.async.wait_group %0;" :: "n"(N) : "memory");
}
__device__ __forceinline__ void mma_f16(float* c, const uint32_t* a, const uint32_t* b) {
    asm volatile("mma.sync.aligned.m16n8k16.row.col.f32.f16.f16.f32 "
        "{%0,%1,%2,%3}, {%4,%5,%6,%7}, {%8,%9}, {%0,%1,%2,%3};"
        : "+f"(c[0]), "+f"(c[1]), "+f"(c[2]), "+f"(c[3])
        : "r"(a[0]), "r"(a[1]), "r"(a[2]), "r"(a[3]), "r"(b[0]), "r"(b[1]));
}

// ---- fp16 fragment-native layout addressing (half-element index) -----------
// A block: 16 rows x 16 k = 256 halfs. b32 quad per (g,tg):
//   {(g,2tg),(g+8,2tg),(g,2tg+8),(g+8,2tg+8)}
__device__ __forceinline__ size_t afh_idx(int r, int k, int KC16) {
    size_t blk = (size_t)((r >> 4) * KC16 + (k >> 4));
    int b32 = (r & 7) * 16 + ((k >> 1) & 3) * 4 + ((r >> 3) & 1) + 2 * ((k >> 3) & 1);
    return blk * 256 + b32 * 2 + (k & 1);
}
// B block: 8 n x 16 k = 128 halfs. b32 pair per (g,tg): {(n=g,2tg),(n=g,2tg+8)}
// inverse map for out-index -> (n, k) used by coalesced-write format kernels:
__device__ __forceinline__ void bfh_inv(int idx, int KC16, int& n, int& k) {
    int blk = idx >> 7;
    int within = idx & 127;
    int b32 = within >> 1, h = within & 1;
    int nb = blk / KC16, kb = blk % KC16;
    n = nb * 8 + (b32 >> 3);
    k = (kb << 4) | ((b32 & 1) << 3) | (((b32 >> 1) & 3) << 1) | h;
}

// ======================= scratch ============================================
__device__ __align__(256) __half g_xn    [NROWS * DM];   // A_f in-proj  (K=768)
__device__ __align__(256) __half g_xin   [NROWS * EE];   // row-major fp16
__device__ __align__(256) __half g_xact  [NROWS * EE];   // A_f packed   (K=1536)
__device__ __align__(256) __half g_cat   [NROWS * EE];   // A_f out-proj (K=1536)
__device__ __align__(256) float  g_xd    [NROWS * NPACK];
__device__ float g_dt [NROWS * DS];
__device__ float g_bt [NROWS * DS];
__device__ float g_v  [NROWS * DS];
__device__ float g_bpack[NPACK];
__device__ __align__(256) __half g_winF  [EE * DM];      // B_f: N=1536, K=768
__device__ __align__(256) __half g_wpackF[NPAD * EE];    // B_f: N=896,  K=1536
__device__ __align__(256) __half g_woutF [DM * EE];      // B_f: N=768,  K=1536

// ======================= fp16 mma.sync GEMM =================================
// C[M, Ndim] = Af(M,K) @ Bf(N,K)^T + bias. Output type templated (fp32/fp16).
// Block 128x128, K-chunk 32, 4-stage cp.async, ONE sync per chunk.
template<typename OutT>
__global__ __launch_bounds__(256, 2) void gemm_f16_kernel(
    const __half* __restrict__ Af, const __half* __restrict__ Bf,
    const float* __restrict__ bias, OutT* __restrict__ C,
    int ldc, int Ndim, int K)
{
    extern __shared__ __align__(16) char sm[];
    const int tid = threadIdx.x;
    const int wid = tid >> 5, lane = tid & 31;
    const int wm = wid >> 1, wn = wid & 1;
    const int g = lane >> 2, tg = lane & 3;
    const int KC16 = K >> 4, NC = K >> 5;
    const int mp0 = blockIdx.y * 8;
    const int ng0 = blockIdx.x * 16;
    const int m0 = blockIdx.y * 128, n0 = blockIdx.x * 128;
    const uint32_t smb = smem_u32(sm);

    const __half* a_src0 = Af + ((size_t)(mp0 + (tid >> 6)) * KC16) * 256 + (tid & 63) * 8;
    const __half* a_src1 = Af + ((size_t)(mp0 + (tid >> 6) + 4) * KC16) * 256 + (tid & 63) * 8;
    const __half* b_src0 = Bf + ((size_t)(ng0 + (tid >> 5)) * KC16) * 128 + (tid & 31) * 8;
    const __half* b_src1 = Bf + ((size_t)(ng0 + (tid >> 5) + 8) * KC16) * 128 + (tid & 31) * 8;
    const uint32_t a_dst0 = smb + (uint32_t)tid * 16u;
    const uint32_t a_dst1 = smb + (uint32_t)(tid + 256) * 16u;
    const uint32_t b_dst0 = smb + 8192u + (uint32_t)tid * 16u;
    const uint32_t b_dst1 = smb + 8192u + (uint32_t)(tid + 256) * 16u;

    auto load_chunk = [&](int c) {
        const uint32_t st = (uint32_t)(c & 3) * STAGE_BYTES;
        cp_async16(a_dst0 + st, a_src0 + (size_t)c * 512);
        cp_async16(a_dst1 + st, a_src1 + (size_t)c * 512);
        cp_async16(b_dst0 + st, b_src0 + (size_t)c * 256);
        cp_async16(b_dst1 + st, b_src1 + (size_t)c * 256);
        cp_commit();
    };

    float acc[2][8][4];
    #pragma unroll
    for (int mi = 0; mi < 2; mi++)
        #pragma unroll
        for (int ni = 0; ni < 8; ni++)
            #pragma unroll
            for (int q = 0; q < 4; q++) acc[mi][ni][q] = 0.0f;

    load_chunk(0); load_chunk(1); load_chunk(2);

    const char* stA_base = sm + wm * 2048 + g * 64 + tg * 16;
    const char* stB_base = sm + 8192 + wn * 4096 + g * 32 + tg * 8;

    for (int c = 0; c < NC; c++) {
        cp_wait<2>();                 // chunk c resident
        __syncthreads();              // all warps done with chunk c-1 (stage (c+3)&3)
        if (c + 3 < NC) load_chunk(c + 3); else cp_commit();

        const char* stA = stA_base + (c & 3) * STAGE_BYTES;
        const char* stB = stB_base + (c & 3) * STAGE_BYTES;

        #pragma unroll
        for (int kb = 0; kb < 2; kb++) {
            uint4 a0 = *(const uint4*)(stA + kb * 512);
            uint4 a1 = *(const uint4*)(stA + 1024 + kb * 512);
            uint2 bq[8];
            #pragma unroll
            for (int ni = 0; ni < 8; ni++)
                bq[ni] = *(const uint2*)(stB + ni * 512 + kb * 256);
            #pragma unroll
            for (int ni = 0; ni < 8; ni++) {
                mma_f16(acc[0][ni], (const uint32_t*)&a0, (const uint32_t*)&bq[ni]);
                mma_f16(acc[1][ni], (const uint32_t*)&a1, (const uint32_t*)&bq[ni]);
            }
        }
    }

    // ---- epilogue ------------------------------------------------------------
    #pragma unroll
    for (int mi = 0; mi < 2; mi++) {
        const int row = m0 + wm * 32 + mi * 16 + g;
        OutT* c0 = C + (size_t)row * ldc;
        OutT* c1 = C + (size_t)(row + 8) * ldc;
        #pragma unroll
        for (int ni = 0; ni < 8; ni++) {
            const int col = n0 + wn * 64 + ni * 8 + tg * 2;
            if (col < Ndim) {
                float bx = bias[col], by = bias[col + 1];
                float v00 = acc[mi][ni][0] + bx, v01 = acc[mi][ni][1] + by;
                float v10 = acc[mi][ni][2] + bx, v11 = acc[mi][ni][3] + by;
                if (sizeof(OutT) == 2) {
                    *(__half2*)((__half*)c0 + col) = __floats2half2_rn(v00, v01);
                    *(__half2*)((__half*)c1 + col) = __floats2half2_rn(v10, v11);
                } else {
                    *(float2*)((float*)c0 + col) = make_float2(v00, v01);
                    *(float2*)((float*)c1 + col) = make_float2(v10, v11);
                }
            }
        }
    }
}

// ======================= LayerNorm -> A_f fp16 (K=768) ======================
__global__ __launch_bounds__(256) void ln_kernel(const float* __restrict__ x,
                                                 const float* __restrict__ g,
                                                 const float* __restrict__ b) {
    int row = blockIdx.x, tid = threadIdx.x;
    const float* xr = x + (size_t)row * DM;
    float v0 = xr[tid], v1 = xr[tid + 256], v2 = xr[tid + 512];
    __shared__ float red[256];
    red[tid] = v0 + v1 + v2; __syncthreads();
    for (int off = 128; off > 0; off >>= 1) {
        if (tid < off) red[tid] += red[tid + off];
        __syncthreads();
    }
    float mu = red[0] * (1.0f / DM); __syncthreads();
    float d0 = v0 - mu, d1 = v1 - mu, d2 = v2 - mu;
    red[tid] = d0*d0 + d1*d1 + d2*d2; __syncthreads();
    for (int off = 128; off > 0; off >>= 1) {
        if (tid < off) red[tid] += red[tid + off];
        __syncthreads();
    }
    float rstd = rsqrtf(red[0] * (1.0f / DM) + LN_EPS);
    g_xn[afh_idx(row, tid,       48)] = __float2half_rn(d0 * rstd * g[tid]       + b[tid]);
    g_xn[afh_idx(row, tid + 256, 48)] = __float2half_rn(d1 * rstd * g[tid + 256] + b[tid + 256]);
    g_xn[afh_idx(row, tid + 512, 48)] = __float2half_rn(d2 * rstd * g[tid + 512] + b[tid + 512]);
}

// ======================= weight format kernels (coalesced writes) ===========
__global__ void bfmt_kernel(const float* __restrict__ W, __half* __restrict__ Bf,
                            int N, int KC16) {  // W row-major [K][N]
    int idx = blockIdx.x * blockDim.x + threadIdx.x;
    int n, k; bfh_inv(idx, KC16, n, k);
    Bf[idx] = __float2half_rn(W[(size_t)k * N + n]);
}

__global__ void bfmt_pack_kernel(const float* __restrict__ W_xp,
                                 const float* __restrict__ W_dt,
                                 const float* __restrict__ b_xp,
                                 const float* __restrict__ b_dt) {
    int idx = blockIdx.x * blockDim.x + threadIdx.x;
    if (idx < NPAD * EE) {
        int n, k; bfh_inv(idx, 96, n, k);
        float v = (n < DM + DS) ? W_xp[(size_t)k * (DM + DS) + n]
                : (n < NPACK)   ? W_dt[(size_t)k * DS + (n - (DM + DS))]
                : 0.0f;
        g_wpackF[idx] = __float2half_rn(v);
    }
    if (idx < NPACK)
        g_bpack[idx] = (idx < DM + DS) ? b_xp[idx] : b_dt[idx - (DM + DS)];
}

// ======================= depthwise conv (k=4) + SiLU -> A_f fp16 ============
__global__ void conv_silu_kernel(const float* __restrict__ b_conv,
                                 const float* __restrict__ W_conv) {
    int idx = blockIdx.x * blockDim.x + threadIdx.x;
    if (idx >= (NROWS / 4) * EE) return;
    int e = idx % EE;
    int r0 = (idx / EE) * 4;
    int l0 = r0 % Lseq;
    const float4 w = *(const float4*)(W_conv + e * 4);
    float bc = b_conv[e];
    float x0 = (l0 >= 3) ? __half2float(g_xin[(size_t)(r0 - 3) * EE + e]) : 0.f;
    float x1 = (l0 >= 2) ? __half2float(g_xin[(size_t)(r0 - 2) * EE + e]) : 0.f;
    float x2 = (l0 >= 1) ? __half2float(g_xin[(size_t)(r0 - 1) * EE + e]) : 0.f;
    float x3 = __half2float(g_xin[(size_t)(r0 + 0) * EE + e]);
    float x4 = __half2float(g_xin[(size_t)(r0 + 1) * EE + e]);
    float x5 = __half2float(g_xin[(size_t)(r0 + 2) * EE + e]);
    float x6 = __half2float(g_xin[(size_t)(r0 + 3) * EE + e]);
    float s0 = bc + x0 * w.x + x1 * w.y + x2 * w.z + x3 * w.w;
    float s1 = bc + x1 * w.x + x2 * w.y + x3 * w.z + x4 * w.w;
    float s2 = bc + x2 * w.x + x3 * w.y + x4 * w.z + x5 * w.w;
    float s3 = bc + x3 * w.x + x4 * w.y + x5 * w.z + x6 * w.w;
    __half a0 = __float2half_rn(s0 / (1.0f + expf(-s0)));
    __half a1 = __float2half_rn(s1 / (1.0f + expf(-s1)));
    __half a2 = __float2half_rn(s2 / (1.0f + expf(-s2)));
    __half a3 = __float2half_rn(s3 / (1.0f + expf(-s3)));
    g_xact[afh_idx(r0 + 0, e, 96)] = a0;
    g_xact[afh_idx(r0 + 1, e, 96)] = a1;
    g_xact[afh_idx(r0 + 2, e, 96)] = a2;
    g_xact[afh_idx(r0 + 3, e, 96)] = a3;
    if (e >= DM) {
        g_cat[afh_idx(r0 + 0, e, 96)] = a0;
        g_cat[afh_idx(r0 + 1, e, 96)] = a1;
        g_cat[afh_idx(r0 + 2, e, 96)] = a2;
        g_cat[afh_idx(r0 + 3, e, 96)] = a3;
    }
}

// ======================= fused prescan + parallel scan ======================
__global__ __launch_bounds__(256) void scan_kernel() {
    int chan = blockIdx.x;
    int bb = chan / DS, s = chan % DS;
    int t = threadIdx.x;
    __shared__ float sA[256], sB[256];
    float A = 1.0f, Bl = 0.0f;
    int base = bb * Lseq;
    #pragma unroll 4
    for (int i = 0; i < 16; i++) {
        size_t rofs = (size_t)(base + t * 16 + i);
        float dtraw = g_xd[rofs * NPACK + (DM + DS) + s];
        float ds    = g_xd[rofs * NPACK + DM + s];
        float dt = fmaxf(dtraw, 0.0f) + log1pf(expf(-fabsf(dtraw)));
        float bt = ds * expf(-0.5f * dt);
        g_dt[rofs * DS + s] = dt;
        g_bt[rofs * DS + s] = bt;
        float a = expf(-dt);
        Bl = a * Bl + bt;
        A = a * A;
    }
    sA[t] = A; sB[t] = Bl;
    __syncthreads();
    for (int offp = 1; offp < 256; offp <<= 1) {
        float pA = 0.f, pB = 0.f;
        bool has = (t >= offp);
        if (has) { pA = sA[t - offp]; pB = sB[t - offp]; }
        __syncthreads();
        if (has) { sB[t] = sA[t] * pB + sB[t]; sA[t] = sA[t] * pA; }
        __syncthreads();
    }
    float v = (t == 0) ? 0.0f : sB[t - 1];
    for (int i = 0; i < 16; i++) {
        size_t off = (size_t)(base + t * 16 + i) * DS + s;
        float a = expf(-g_dt[off]);
        v = a * v + g_bt[off];
        g_v[off] = v;
    }
}

// ======================= us + xs + us@W_us -> g_cat fp16 (K=1536) ===========
__global__ __launch_bounds__(256) void us_y_kernel(const float* __restrict__ W_us,
                                                   const float* __restrict__ b_us) {
    int row = blockIdx.x, tid = threadIdx.x;
    int l = row % Lseq;
    float kf = (float)(Lseq - 1 - l);
    __shared__ float us_sh[DS];
    if (tid < DS) {
        size_t off = (size_t)row * DS + tid;
        float dt = g_dt[off], v = g_v[off], bt = g_bt[off];
        float denom = expm1f(-dt);
        if (denom > -1e-30f) denom = -1e-30f;
        us_sh[tid] = expf(-kf * dt) * v + bt * expm1f(-kf * dt) / denom;
    }
    __syncthreads();
    #pragma unroll
    for (int j = 0; j < 3; j++) {
        int d = tid + j * 256;
        float acc = g_xd[(size_t)row * NPACK + d] + b_us[d];
        #pragma unroll
        for (int s = 0; s < DS; s++)
            acc = fmaf(us_sh[s], W_us[s * DM + d], acc);
        g_cat[afh_idx(row, d, 96)] = __float2half_rn(acc);
    }
}

// ======================= launch =============================================
extern "C" void kernel_launch(void* const* d_in, const int* in_sizes, int n_in,
                              void* d_out, int out_size) {
    const float* x      = (const float*)d_in[0];
    const float* ln_g   = (const float*)d_in[1];
    const float* ln_b   = (const float*)d_in[2];
    const float* W_in   = (const float*)d_in[3];
    const float* b_in   = (const float*)d_in[4];
    const float* W_conv = (const float*)d_in[5];
    const float* b_conv = (const float*)d_in[6];
    const float* W_xp   = (const float*)d_in[7];
    const float* b_xp   = (const float*)d_in[8];
    const float* W_dt   = (const float*)d_in[9];
    const float* b_dt   = (const float*)d_in[10];
    const float* W_us   = (const float*)d_in[11];
    const float* b_us   = (const float*)d_in[12];
    const float* W_out  = (const float*)d_in[13];
    const float* b_out  = (const float*)d_in[14];
    float* out = (float*)d_out;

    __half* xn  ; cudaGetSymbolAddress((void**)&xn,    g_xn);
    __half* xin ; cudaGetSymbolAddress((void**)&xin,   g_xin);
    __half* xact; cudaGetSymbolAddress((void**)&xact,  g_xact);
    __half* cat ; cudaGetSymbolAddress((void**)&cat,   g_cat);
    float*  xd  ; cudaGetSymbolAddress((void**)&xd,    g_xd);
    float* bpack; cudaGetSymbolAddress((void**)&bpack, g_bpack);
    __half* winF ; cudaGetSymbolAddress((void**)&winF,  g_winF);
    __half* wpF  ; cudaGetSymbolAddress((void**)&wpF,   g_wpackF);
    __half* woutF; cudaGetSymbolAddress((void**)&woutF, g_woutF);

    const int GEMM_SMEM = STAGES * STAGE_BYTES;  // 65536
    cudaFuncSetAttribute(gemm_f16_kernel<__half>,
                         cudaFuncAttributeMaxDynamicSharedMemorySize, GEMM_SMEM);
    cudaFuncSetAttribute(gemm_f16_kernel<float>,
                         cudaFuncAttributeMaxDynamicSharedMemorySize, GEMM_SMEM);

    // weight formatting (independent of activations)
    bfmt_kernel<<<(EE * DM) / 256, 256>>>(W_in, winF, EE, 48);    // N=1536, K=768
    bfmt_kernel<<<(DM * EE) / 256, 256>>>(W_out, woutF, DM, 96);  // N=768,  K=1536
    bfmt_pack_kernel<<<(NPAD * EE + 255) / 256, 256>>>(W_xp, W_dt, b_xp, b_dt);

    // 1. LayerNorm -> A_f
    ln_kernel<<<NROWS, 256>>>(x, ln_g, ln_b);

    // 2. in-proj: (8192x768) @ (768x1536) -> xin (fp16 row-major)
    gemm_f16_kernel<__half><<<dim3(EE/128, NROWS/128), 256, GEMM_SMEM>>>(
        xn, winF, b_in, xin, EE, EE, DM);

    // 3. conv + silu -> xact A_f (+ upper half into g_cat A_f)
    conv_silu_kernel<<<((NROWS/4) * EE + 255) / 256, 256>>>(b_conv, W_conv);

    // 4. packed proj: (8192x1536) @ (1536x800) -> xd (fp32 row-major)
    gemm_f16_kernel<float><<<dim3(NPAD/128, NROWS/128), 256, GEMM_SMEM>>>(
        xact, wpF, bpack, xd, NPACK, NPACK, EE);

    // 5-6. fused prescan+scan, then us_y
    scan_kernel<<<Bsz * DS, 256>>>();
    us_y_kernel<<<NROWS, 256>>>(W_us, b_us);

    // 7. out-proj: (8192x1536) @ (1536x768) -> out
    gemm_f16_kernel<float><<<dim3(DM/128, NROWS/128), 256, GEMM_SMEM>>>(
        cat, woutF, b_out, out, DM, DM, EE);
}